// round 16
// baseline (speedup 1.0000x reference)
#include <cuda_runtime.h>
#include <cuda_fp16.h>
#include <math.h>
#include <stdint.h>

// Problem constants (fixed by the reference)
#define DM   1024
#define SQ   2048
#define BB   4
#define HH   16
#define HD   64
#define NTOK (BB * SQ)   // 8192

// ---------------------------------------------------------------------------
// Scratch (device globals; no dynamic allocation allowed)
// ---------------------------------------------------------------------------
__device__ float  g_xpe[NTOK * DM];      // x + pe, fp32 (residual)
__device__ __half g_xh [NTOK * DM];      // x + pe, fp16 (GEMM A)
__device__ __half g_wTh[4 * DM * DM];    // transposed fp16 weights [N][K]
__device__ __half g_qh [NTOK * DM];
__device__ __half g_kh [NTOK * DM];
__device__ __half g_vh [NTOK * DM];
__device__ __half g_ah [NTOK * DM];      // attention out, fp16

// ---------------------------------------------------------------------------
// helpers
// ---------------------------------------------------------------------------
__device__ __forceinline__ uint32_t smem_u32(const void* p) {
    uint32_t a;
    asm("{ .reg .u64 t; cvta.to.shared.u64 t, %1; cvt.u32.u64 %0, t; }" : "=r"(a) : "l"(p));
    return a;
}

#define CP_ASYNC16(saddr, gptr) \
    asm volatile("cp.async.cg.shared.global [%0], [%1], 16;" :: "r"(saddr), "l"(gptr))
#define CP_COMMIT() asm volatile("cp.async.commit_group;" ::: "memory")
#define CP_WAIT1()  asm volatile("cp.async.wait_group 1;" ::: "memory")
#define CP_WAIT0()  asm volatile("cp.async.wait_group 0;" ::: "memory")

#define LDSM_X4(r0, r1, r2, r3, addr) \
    asm volatile("ldmatrix.sync.aligned.m8n8.x4.shared.b16 {%0,%1,%2,%3}, [%4];" \
                 : "=r"(r0), "=r"(r1), "=r"(r2), "=r"(r3) : "r"(addr))
#define LDSM_X2(r0, r1, addr) \
    asm volatile("ldmatrix.sync.aligned.m8n8.x2.shared.b16 {%0,%1}, [%2];" \
                 : "=r"(r0), "=r"(r1) : "r"(addr))
#define LDSM_X2_TRANS(r0, r1, addr) \
    asm volatile("ldmatrix.sync.aligned.m8n8.x2.trans.shared.b16 {%0,%1}, [%2];" \
                 : "=r"(r0), "=r"(r1) : "r"(addr))

// D(f32x4) += A(f16 m16k16) * B(f16 k16n8)
__device__ __forceinline__ void mma_f16(float& d0, float& d1, float& d2, float& d3,
    uint32_t a0, uint32_t a1, uint32_t a2, uint32_t a3, uint32_t b0, uint32_t b1)
{
    asm volatile("mma.sync.aligned.m16n8k16.row.col.f32.f16.f16.f32 "
        "{%0,%1,%2,%3}, {%4,%5,%6,%7}, {%8,%9}, {%0,%1,%2,%3};"
        : "+f"(d0), "+f"(d1), "+f"(d2), "+f"(d3)
        : "r"(a0), "r"(a1), "r"(a2), "r"(a3), "r"(b0), "r"(b1));
}

// ---------------------------------------------------------------------------
// 1) x + pe -> fp32 copy (residual) + fp16 copy (GEMM A)
// ---------------------------------------------------------------------------
__global__ __launch_bounds__(256) void add_pe_kernel(const float* __restrict__ x,
                                                     const float* __restrict__ pe) {
    int i = blockIdx.x * blockDim.x + threadIdx.x;  // float4 index
    float4 xv = reinterpret_cast<const float4*>(x)[i];
    int d4  = i & (DM / 4 - 1);
    int tok = i >> 8;
    int s   = tok & (SQ - 1);
    float4 pv = reinterpret_cast<const float4*>(pe)[s * (DM / 4) + d4];
    xv.x += pv.x; xv.y += pv.y; xv.z += pv.z; xv.w += pv.w;
    reinterpret_cast<float4*>(g_xpe)[i] = xv;
    __half2 h0 = __floats2half2_rn(xv.x, xv.y);
    __half2 h1 = __floats2half2_rn(xv.z, xv.w);
    reinterpret_cast<__half2*>(g_xh)[i * 2 + 0] = h0;
    reinterpret_cast<__half2*>(g_xh)[i * 2 + 1] = h1;
}

// ---------------------------------------------------------------------------
// 1b) all 4 weight transposes in one launch: WT[z][n][k] = half(Wz[k][n])
// ---------------------------------------------------------------------------
__global__ __launch_bounds__(256) void transpose_w_kernel(
    const float* __restrict__ w0, const float* __restrict__ w1,
    const float* __restrict__ w2, const float* __restrict__ w3) {
    __shared__ float t[32][33];
    const float* W = (blockIdx.z == 0) ? w0 : (blockIdx.z == 1) ? w1
                   : (blockIdx.z == 2) ? w2 : w3;
    __half* WT = g_wTh + (size_t)blockIdx.z * DM * DM;
    int tx = threadIdx.x, ty = threadIdx.y;       // 32 x 8
    int x = blockIdx.x * 32 + tx;                 // n
    int y = blockIdx.y * 32 + ty;                 // k
#pragma unroll
    for (int i = 0; i < 32; i += 8)
        t[ty + i][tx] = W[(size_t)(y + i) * DM + x];
    __syncthreads();
    int x2 = blockIdx.y * 32 + tx;                // k
    int y2 = blockIdx.x * 32 + ty;                // n
#pragma unroll
    for (int i = 0; i < 32; i += 8)
        WT[(size_t)(y2 + i) * DM + x2] = __float2half(t[tx][ty + i]);
}

// ---------------------------------------------------------------------------
// 2) fp16 tensor-core GEMM, 128x128 CTA tile, 8 warps of 64x32, BK=64,
//    cp.async double buffer, ldmatrix fragment loads.
//    QKV mode: blockIdx.x in [0,24): mat = x>>3 selects (WT,bias,out), half out.
//    O mode:   single matrix, fp32 out = acc + bias + residual.
// ---------------------------------------------------------------------------
#define HG_STRIDE 72                      // halfs per smem row
#define HG_BUF    (128 * HG_STRIDE)      // halfs per matrix buffer

template <bool QKV>
__global__ __launch_bounds__(256) void hgemm_kernel(
    const __half* __restrict__ A, const __half* __restrict__ WT,
    const float* __restrict__ b0, const float* __restrict__ b1,
    const float* __restrict__ b2, const float* __restrict__ R,
    void* o0, void* o1, void* o2)
{
    extern __shared__ __half hsm[];
    __half* As = hsm;                     // [2][128][72]
    __half* Bs = hsm + 2 * HG_BUF;        // [2][128][72]

    const int tid = threadIdx.x;
    const int wid = tid >> 5, lane = tid & 31;
    const int r = lane >> 2, cq = lane & 3;
    const int wm = (wid >> 2) * 64;       // warp m offset
    const int wn = (wid & 3) * 32;        // warp n offset
    const int m0 = blockIdx.y * 128;

    int mat, n0;
    if (QKV) { mat = blockIdx.x >> 3; n0 = (blockIdx.x & 7) * 128; }
    else     { mat = 0;               n0 = blockIdx.x * 128; }
    const __half* BT = WT + (QKV ? (size_t)mat * DM * DM : 0);
    const float* bias = QKV ? (mat == 0 ? b0 : (mat == 1 ? b1 : b2)) : b0;
    void* Cout = QKV ? (mat == 0 ? o0 : (mat == 1 ? o1 : o2)) : o0;

    // cp.async geometry: tile 128 rows x 64 halfs = 8 chunks/row; 4 chunks/thread
    const __half* ag[4]; const __half* bg[4]; uint32_t so[4];
#pragma unroll
    for (int i = 0; i < 4; ++i) {
        int idx = i * 256 + tid;
        int row = idx >> 3, c8 = idx & 7;
        ag[i] = A  + (size_t)(m0 + row) * DM + c8 * 8;
        bg[i] = BT + (size_t)(n0 + row) * DM + c8 * 8;
        so[i] = (uint32_t)(row * HG_STRIDE + c8 * 8) * 2;   // bytes
    }
    const uint32_t As_u = smem_u32(As), Bs_u = smem_u32(Bs);

    // ldmatrix lane addressing (bytes, sans buffer/kt offset)
    const int aRow = lane & 15, aC8 = (lane >> 4) * 8;
    const int bIdx = lane & 15, bRow = bIdx & 7, bC8 = (bIdx >> 3) * 8;
    uint32_t aOff[4], bOff[4];
#pragma unroll
    for (int mt = 0; mt < 4; ++mt)
        aOff[mt] = (uint32_t)((wm + mt * 16 + aRow) * HG_STRIDE + aC8) * 2;
#pragma unroll
    for (int nt = 0; nt < 4; ++nt)
        bOff[nt] = (uint32_t)((wn + nt * 8 + bRow) * HG_STRIDE + bC8) * 2;

    float acc[16][4] = {};   // [mt*4+nt]

    // prologue: buffer 0, k=0
#pragma unroll
    for (int i = 0; i < 4; ++i) {
        CP_ASYNC16(As_u + so[i], ag[i]);
        CP_ASYNC16(Bs_u + so[i], bg[i]);
    }
    CP_COMMIT();

    for (int s = 0; s < 16; ++s) {        // K = 1024, BK = 64
        const int buf = s & 1;
        if (s + 1 < 16) {
            const int ob = buf ^ 1;
            const int koff = (s + 1) * 64;
#pragma unroll
            for (int i = 0; i < 4; ++i) {
                CP_ASYNC16(As_u + (uint32_t)(ob * HG_BUF * 2) + so[i], ag[i] + koff);
                CP_ASYNC16(Bs_u + (uint32_t)(ob * HG_BUF * 2) + so[i], bg[i] + koff);
            }
            CP_COMMIT();
            CP_WAIT1();
        } else {
            CP_WAIT0();
        }
        __syncthreads();

        const uint32_t Ab = As_u + (uint32_t)(buf * HG_BUF * 2);
        const uint32_t Bb = Bs_u + (uint32_t)(buf * HG_BUF * 2);

#pragma unroll
        for (int kt = 0; kt < 4; ++kt) {          // 4 x k16
            const uint32_t ko = kt * 32;          // 16 halfs
            uint32_t af[4][4], bf[4][2];
#pragma unroll
            for (int mt = 0; mt < 4; ++mt)
                LDSM_X4(af[mt][0], af[mt][1], af[mt][2], af[mt][3], Ab + aOff[mt] + ko);
#pragma unroll
            for (int nt = 0; nt < 4; ++nt)
                LDSM_X2(bf[nt][0], bf[nt][1], Bb + bOff[nt] + ko);
#pragma unroll
            for (int mt = 0; mt < 4; ++mt)
#pragma unroll
                for (int nt = 0; nt < 4; ++nt)
                    mma_f16(acc[mt * 4 + nt][0], acc[mt * 4 + nt][1],
                            acc[mt * 4 + nt][2], acc[mt * 4 + nt][3],
                            af[mt][0], af[mt][1], af[mt][2], af[mt][3],
                            bf[nt][0], bf[nt][1]);
        }
        __syncthreads();
    }

    // epilogue
#pragma unroll
    for (int mt = 0; mt < 4; ++mt) {
        const int row0 = m0 + wm + mt * 16 + r;
#pragma unroll
        for (int nt = 0; nt < 4; ++nt) {
            const int col = n0 + wn + nt * 8 + cq * 2;
            float2 bv = *reinterpret_cast<const float2*>(&bias[col]);
            float* a4 = acc[mt * 4 + nt];
            float v00 = a4[0] + bv.x, v01 = a4[1] + bv.y;
            float v10 = a4[2] + bv.x, v11 = a4[3] + bv.y;
            if (QKV) {
                __half* C = (__half*)Cout;
                *reinterpret_cast<__half2*>(&C[(size_t)row0 * DM + col]) =
                    __floats2half2_rn(v00, v01);
                *reinterpret_cast<__half2*>(&C[(size_t)(row0 + 8) * DM + col]) =
                    __floats2half2_rn(v10, v11);
            } else {
                float* C = (float*)Cout;
                float2 r0v = *reinterpret_cast<const float2*>(&R[(size_t)row0 * DM + col]);
                float2 r1v = *reinterpret_cast<const float2*>(&R[(size_t)(row0 + 8) * DM + col]);
                *reinterpret_cast<float2*>(&C[(size_t)row0 * DM + col]) =
                    make_float2(v00 + r0v.x, v01 + r0v.y);
                *reinterpret_cast<float2*>(&C[(size_t)(row0 + 8) * DM + col]) =
                    make_float2(v10 + r1v.x, v11 + r1v.y);
            }
        }
    }
}

// ---------------------------------------------------------------------------
// 3) Flash attention, fp16 mma + h2exp2 softmax, ldmatrix frag loads.
//    Block: 128 thr (4 warps x 16 q-rows = 64 q-rows), K-tiles of 64.
//    Small CTAs -> 4 CTAs/SM resident; independent CTAs decorrelate softmax
//    phases so HMMA gaps are covered. V via ldmatrix.trans from [s][d].
// ---------------------------------------------------------------------------
#define FQ_H   (64 * 72)    // Q halfs
#define FK_H   (64 * 72)    // K halfs per buffer
#define FV_H   (64 * 72)    // V halfs per buffer
#define F_SMEM ((FQ_H + 2 * FK_H + 2 * FV_H) * 2)   // 46080 bytes

__global__ __launch_bounds__(128) void flash_kernel() {
    extern __shared__ __half hsm[];
    __half* Qs  = hsm;                       // [64][72]
    __half* Ksm = hsm + FQ_H;                // [2][64][72]
    __half* Vsm = hsm + FQ_H + 2 * FK_H;     // [2][64][72]  ([s][d])

    const int qt = blockIdx.x, h = blockIdx.y, b = blockIdx.z;
    const int tid = threadIdx.x, wid = tid >> 5, lane = tid & 31;
    const int r = lane >> 2, cq = lane & 3;
    const int q0 = qt * 64;

    const __half* Qg = g_qh + (size_t)b * SQ * DM + h * HD;
    const __half* Kg = g_kh + (size_t)b * SQ * DM + h * HD;
    const __half* Vg = g_vh + (size_t)b * SQ * DM + h * HD;

    // load Q tile [64][64]: 512 chunks / 128 thr = 4 each
    for (int idx = tid; idx < 64 * 8; idx += 128) {
        int row = idx >> 3, c8 = idx & 7;
        *reinterpret_cast<uint4*>(&Qs[row * 72 + c8 * 8]) =
            *reinterpret_cast<const uint4*>(&Qg[(size_t)(q0 + row) * DM + c8 * 8]);
    }

    // cp.async geometry: chunk i covers row i*16 + (tid>>3), col (tid&7)*8
    const int ldRow = tid >> 3, ldC8 = tid & 7;
    const __half* kbase = Kg + (size_t)ldRow * DM + ldC8 * 8;
    const __half* vbase = Vg + (size_t)ldRow * DM + ldC8 * 8;
    const uint32_t kvo0 = (uint32_t)(ldRow * 72 + ldC8 * 8) * 2;
    const uint32_t Ks_u = smem_u32(Ksm), Vs_u = smem_u32(Vsm);
    const uint32_t Qs_u = smem_u32(Qs);

    // ldmatrix lane addressing
    const int aRow = lane & 15, aC8 = (lane >> 4) * 8;
    const int bIdx = lane & 15, bRow = bIdx & 7, bC8 = (bIdx >> 3) * 8;
    uint32_t kOff[8];
#pragma unroll
    for (int nt = 0; nt < 8; ++nt)
        kOff[nt] = (uint32_t)((nt * 8 + bRow) * 72 + bC8) * 2;
    // V trans-load addressing: lane 0..15 -> s-row (jt*16 + bIdx), col d (dt*8)
    const uint32_t vtBase = (uint32_t)(bIdx * 72) * 2;

    __syncthreads();   // Q visible

    // preload Q fragments (4 k16-tiles) via ldmatrix
    uint32_t qa[4][4];
    {
        const uint32_t qbase = Qs_u + (uint32_t)((wid * 16 + aRow) * 72 + aC8) * 2;
#pragma unroll
        for (int kt = 0; kt < 4; ++kt)
            LDSM_X4(qa[kt][0], qa[kt][1], qa[kt][2], qa[kt][3], qbase + kt * 32);
    }

    // prologue: tile 0 into buffer 0 (4 chunks each for K and V)
#pragma unroll
    for (int i = 0; i < 4; ++i) {
        CP_ASYNC16(Ks_u + kvo0 + (uint32_t)(i * 16 * 72 * 2), kbase + (size_t)i * 16 * DM);
        CP_ASYNC16(Vs_u + kvo0 + (uint32_t)(i * 16 * 72 * 2), vbase + (size_t)i * 16 * DM);
    }
    CP_COMMIT();

    float o[8][4] = {};
    float l0s = 0.f, l1s = 0.f;
    float m0s = -1e30f, m1s = -1e30f;     // running max (log2-scaled domain)
    const float LC = 0.18033688f;         // 0.125 * log2(e)

    for (int t = 0; t < SQ / 64; ++t) {
        const int buf = t & 1;
        if (t + 1 < SQ / 64) {
            const int ob = buf ^ 1;
            const size_t adv = (size_t)(t + 1) * 64 * DM;
#pragma unroll
            for (int i = 0; i < 4; ++i) {
                CP_ASYNC16(Ks_u + (uint32_t)(ob * FK_H * 2) + kvo0 + (uint32_t)(i * 16 * 72 * 2),
                           kbase + adv + (size_t)i * 16 * DM);
                CP_ASYNC16(Vs_u + (uint32_t)(ob * FV_H * 2) + kvo0 + (uint32_t)(i * 16 * 72 * 2),
                           vbase + adv + (size_t)i * 16 * DM);
            }
            CP_COMMIT();
            CP_WAIT1();
        } else {
            CP_WAIT0();
        }
        __syncthreads();

        const uint32_t Kb = Ks_u + (uint32_t)(buf * FK_H * 2);
        const uint32_t Vb = Vs_u + (uint32_t)(buf * FV_H * 2);

        // S = Q K^T : 8 n-tiles x 4 k16
        float s[8][4] = {};
#pragma unroll
        for (int nt = 0; nt < 8; ++nt) {
#pragma unroll
            for (int kt = 0; kt < 4; ++kt) {
                uint32_t kf0, kf1;
                LDSM_X2(kf0, kf1, Kb + kOff[nt] + kt * 32);
                mma_f16(s[nt][0], s[nt][1], s[nt][2], s[nt][3],
                        qa[kt][0], qa[kt][1], qa[kt][2], qa[kt][3], kf0, kf1);
            }
        }

        // online softmax (rows r and r+8; reduce over 4 threads sharing each row)
        float rm0 = -1e30f, rm1 = -1e30f;
#pragma unroll
        for (int nt = 0; nt < 8; ++nt) {
            rm0 = fmaxf(rm0, fmaxf(s[nt][0], s[nt][1]));
            rm1 = fmaxf(rm1, fmaxf(s[nt][2], s[nt][3]));
        }
        rm0 = fmaxf(rm0, __shfl_xor_sync(0xffffffffu, rm0, 1));
        rm0 = fmaxf(rm0, __shfl_xor_sync(0xffffffffu, rm0, 2));
        rm1 = fmaxf(rm1, __shfl_xor_sync(0xffffffffu, rm1, 1));
        rm1 = fmaxf(rm1, __shfl_xor_sync(0xffffffffu, rm1, 2));
        const float mn0 = fmaxf(m0s, rm0 * LC);
        const float mn1 = fmaxf(m1s, rm1 * LC);
        const float al0 = exp2f(m0s - mn0);
        const float al1 = exp2f(m1s - mn1);
        m0s = mn0; m1s = mn1;

        // P = exp2(S*LC - m); half2 pairs == fp16 A-fragment registers
        uint32_t ph0[8], ph1[8];
        float rs0 = 0.f, rs1 = 0.f;
#pragma unroll
        for (int nt = 0; nt < 8; ++nt) {
            __half2 e0 = h2exp2(__floats2half2_rn(fmaf(s[nt][0], LC, -mn0),
                                                  fmaf(s[nt][1], LC, -mn0)));
            __half2 e1 = h2exp2(__floats2half2_rn(fmaf(s[nt][2], LC, -mn1),
                                                  fmaf(s[nt][3], LC, -mn1)));
            ph0[nt] = *reinterpret_cast<uint32_t*>(&e0);
            ph1[nt] = *reinterpret_cast<uint32_t*>(&e1);
            float2 f0 = __half22float2(e0);
            float2 f1 = __half22float2(e1);
            rs0 += f0.x + f0.y;
            rs1 += f1.x + f1.y;
        }
        rs0 += __shfl_xor_sync(0xffffffffu, rs0, 1);
        rs0 += __shfl_xor_sync(0xffffffffu, rs0, 2);
        rs1 += __shfl_xor_sync(0xffffffffu, rs1, 1);
        rs1 += __shfl_xor_sync(0xffffffffu, rs1, 2);
        l0s = l0s * al0 + rs0;
        l1s = l1s * al1 + rs1;

        // rescale O by alpha
#pragma unroll
        for (int dt = 0; dt < 8; ++dt) {
            o[dt][0] *= al0; o[dt][1] *= al0;
            o[dt][2] *= al1; o[dt][3] *= al1;
        }

        // O += P @ V   (V [s][d]; trans ldmatrix gives Vt fragments)
#pragma unroll
        for (int jt = 0; jt < 4; ++jt) {
            uint32_t a0 = ph0[2 * jt], a1 = ph1[2 * jt];
            uint32_t a2 = ph0[2 * jt + 1], a3 = ph1[2 * jt + 1];
            const uint32_t vjt = Vb + vtBase + (uint32_t)(jt * 16 * 72 * 2);
#pragma unroll
            for (int dt = 0; dt < 8; ++dt) {
                uint32_t vf0, vf1;
                LDSM_X2_TRANS(vf0, vf1, vjt + dt * 16);
                mma_f16(o[dt][0], o[dt][1], o[dt][2], o[dt][3],
                        a0, a1, a2, a3, vf0, vf1);
            }
        }
        __syncthreads();
    }

    const float inv0 = 1.f / l0s, inv1 = 1.f / l1s;

    __half* Og = g_ah + (size_t)b * SQ * DM + h * HD;
    const int row0 = q0 + wid * 16 + r;
#pragma unroll
    for (int dt = 0; dt < 8; ++dt) {
        const int col = dt * 8 + cq * 2;
        *reinterpret_cast<__half2*>(&Og[(size_t)row0 * DM + col]) =
            __floats2half2_rn(o[dt][0] * inv0, o[dt][1] * inv0);
        *reinterpret_cast<__half2*>(&Og[(size_t)(row0 + 8) * DM + col]) =
            __floats2half2_rn(o[dt][2] * inv1, o[dt][3] * inv1);
    }
}

// ---------------------------------------------------------------------------
// 4) In-place LayerNorm over last dim (1024), one block per row
// ---------------------------------------------------------------------------
__global__ __launch_bounds__(256) void layernorm_kernel(float* __restrict__ out,
                                                        const float* __restrict__ gamma,
                                                        const float* __restrict__ beta) {
    const int row = blockIdx.x, tid = threadIdx.x;
    float4* rowp = reinterpret_cast<float4*>(out) + (size_t)row * 256;
    float4 v = rowp[tid];
    float sum = v.x + v.y + v.z + v.w;
    float sq  = v.x * v.x + v.y * v.y + v.z * v.z + v.w * v.w;
#pragma unroll
    for (int off = 16; off; off >>= 1) {
        sum += __shfl_xor_sync(0xffffffffu, sum, off);
        sq  += __shfl_xor_sync(0xffffffffu, sq, off);
    }
    __shared__ float s1[8], s2[8];
    __shared__ float s_mu, s_inv;
    const int wid = tid >> 5, lane = tid & 31;
    if (lane == 0) { s1[wid] = sum; s2[wid] = sq; }
    __syncthreads();
    if (tid == 0) {
        float ts = 0.f, tq = 0.f;
#pragma unroll
        for (int w = 0; w < 8; ++w) { ts += s1[w]; tq += s2[w]; }
        float mu  = ts * (1.f / 1024.f);
        float var = tq * (1.f / 1024.f) - mu * mu;
        s_mu = mu;
        s_inv = rsqrtf(var + 1e-5f);
    }
    __syncthreads();
    const float mu = s_mu, inv = s_inv;
    float4 g  = reinterpret_cast<const float4*>(gamma)[tid];
    float4 be = reinterpret_cast<const float4*>(beta)[tid];
    v.x = (v.x - mu) * inv * g.x + be.x;
    v.y = (v.y - mu) * inv * g.y + be.y;
    v.z = (v.z - mu) * inv * g.z + be.z;
    v.w = (v.w - mu) * inv * g.w + be.w;
    rowp[tid] = v;
}

// ---------------------------------------------------------------------------
// launch
// ---------------------------------------------------------------------------
extern "C" void kernel_launch(void* const* d_in, const int* in_sizes, int n_in,
                              void* d_out, int out_size) {
    const float* x     = (const float*)d_in[0];
    const float* wq    = (const float*)d_in[1];
    const float* bq    = (const float*)d_in[2];
    const float* wk    = (const float*)d_in[3];
    const float* bk    = (const float*)d_in[4];
    const float* wv    = (const float*)d_in[5];
    const float* bv    = (const float*)d_in[6];
    const float* wo    = (const float*)d_in[7];
    const float* bo    = (const float*)d_in[8];
    const float* gamma = (const float*)d_in[9];
    const float* beta  = (const float*)d_in[10];
    const float* pe    = (const float*)d_in[11];
    float* out = (float*)d_out;

    float *p_xpe;
    __half *p_xh, *p_wT, *p_qh, *p_kh, *p_vh, *p_ah;
    cudaGetSymbolAddress((void**)&p_xpe, g_xpe);
    cudaGetSymbolAddress((void**)&p_xh,  g_xh);
    cudaGetSymbolAddress((void**)&p_wT,  g_wTh);
    cudaGetSymbolAddress((void**)&p_qh,  g_qh);
    cudaGetSymbolAddress((void**)&p_kh,  g_kh);
    cudaGetSymbolAddress((void**)&p_vh,  g_vh);
    cudaGetSymbolAddress((void**)&p_ah,  g_ah);

    // 1) x + pe
    add_pe_kernel<<<NTOK * DM / 4 / 256, 256>>>(x, pe);

    // 1b) transpose + halve all weights (one launch)
    dim3 tb(32, 8);
    transpose_w_kernel<<<dim3(DM / 32, DM / 32, 4), tb>>>(wq, wk, wv, wo);

    // 2) fused Q/K/V projections on tensor cores (half out)
    const int gsmem = 4 * HG_BUF * 2;   // 73728 bytes
    cudaFuncSetAttribute(hgemm_kernel<true>,
                         cudaFuncAttributeMaxDynamicSharedMemorySize, gsmem);
    cudaFuncSetAttribute(hgemm_kernel<false>,
                         cudaFuncAttributeMaxDynamicSharedMemorySize, gsmem);
    hgemm_kernel<true><<<dim3(24, NTOK / 128), 256, gsmem>>>(
        p_xh, p_wT, bq, bk, bv, nullptr, p_qh, p_kh, p_vh);

    // 3) attention: 64-row q-tiles, 128-thread CTAs (4 CTAs/SM resident)
    cudaFuncSetAttribute(flash_kernel,
                         cudaFuncAttributeMaxDynamicSharedMemorySize, F_SMEM);
    flash_kernel<<<dim3(SQ / 64, HH, BB), 128, F_SMEM>>>();

    // 4) output projection + bias + residual -> d_out (fp32)
    hgemm_kernel<false><<<dim3(8, NTOK / 128), 256, gsmem>>>(
        p_ah, p_wT + 3 * (size_t)DM * DM, bo, nullptr, nullptr, p_xpe, out, nullptr, nullptr);

    // 5) in-place layernorm
    layernorm_kernel<<<NTOK, 256>>>(out, gamma, beta);
}